// round 2
// baseline (speedup 1.0000x reference)
#include <cuda_runtime.h>
#include <cuda_fp16.h>
#include <cstdint>

// Problem constants (fixed shapes)
#define K_DIM 4096
#define N_DIM 11008
#define M_DIM 8192
#define NPACK 1376   /* N/8 packed int32 columns */

#define BM 128
#define BN 128
#define BK 32
#define PADA 8
#define PADB 8

// Scratch (static __device__ arrays: allowed)
__device__ __half g_W[(size_t)K_DIM * N_DIM];   // 90 MB dequantized weights (fp16)
__device__ __half g_X[(size_t)M_DIM * K_DIM];   // 64 MB activations converted fp32->fp16

#define CP_ASYNC_CG(dst, src) \
    asm volatile("cp.async.cg.shared.global [%0], [%1], 16;\n" :: "r"(dst), "l"(src))
#define CP_COMMIT() asm volatile("cp.async.commit_group;\n" ::)
#define CP_WAIT(n)  asm volatile("cp.async.wait_group %0;\n" :: "n"(n))

// ---------------------------------------------------------------------------
// Kernel 0: convert x (fp32 from harness) -> fp16 g_X. 8 elements/thread.
// ---------------------------------------------------------------------------
__global__ void convert_x_kernel(const float* __restrict__ x)
{
    size_t i = ((size_t)blockIdx.x * blockDim.x + threadIdx.x) * 8;
    if (i >= (size_t)M_DIM * K_DIM) return;
    float4 f0 = *reinterpret_cast<const float4*>(x + i);
    float4 f1 = *reinterpret_cast<const float4*>(x + i + 4);
    __half h[8];
    h[0] = __float2half(f0.x); h[1] = __float2half(f0.y);
    h[2] = __float2half(f0.z); h[3] = __float2half(f0.w);
    h[4] = __float2half(f1.x); h[5] = __float2half(f1.y);
    h[6] = __float2half(f1.z); h[7] = __float2half(f1.w);
    *reinterpret_cast<uint4*>(&g_X[i]) = *reinterpret_cast<uint4*>(h);
}

// ---------------------------------------------------------------------------
// Kernel 1: AWQ 4-bit dequant -> fp16 g_W[k][n]
// Output col p*8+j takes nibble AWQ_REVERSE_ORDER[j] = {0,4,1,5,2,6,3,7},
// i.e. shifts {0,16,4,20,8,24,12,28}.
// ---------------------------------------------------------------------------
__global__ void dequant_kernel(const int* __restrict__ qw,
                               const int* __restrict__ qz,
                               const float* __restrict__ sc)
{
    int idx = blockIdx.x * blockDim.x + threadIdx.x;
    if (idx >= K_DIM * NPACK) return;
    int k = idx / NPACK;
    int p = idx - k * NPACK;

    int w = qw[idx];
    int z = qz[(k >> 7) * NPACK + p];

    // 8 contiguous fp32 scales (2x 16B vector loads)
    const float* sp = sc + (size_t)(k >> 7) * N_DIM + p * 8;
    float4 s0 = *reinterpret_cast<const float4*>(sp);
    float4 s1 = *reinterpret_cast<const float4*>(sp + 4);
    float sf[8] = {s0.x, s0.y, s0.z, s0.w, s1.x, s1.y, s1.z, s1.w};

    const int shift[8] = {0, 16, 4, 20, 8, 24, 12, 28};
    __half outv[8];
#pragma unroll
    for (int j = 0; j < 8; j++) {
        int iw = (w >> shift[j]) & 15;
        int iz = (z >> shift[j]) & 15;
        outv[j] = __float2half((float)(iw - iz) * sf[j]);
    }
    *reinterpret_cast<uint4*>(&g_W[(size_t)k * N_DIM + p * 8]) =
        *reinterpret_cast<uint4*>(outv);
}

// ---------------------------------------------------------------------------
// Kernel 2: fp16 GEMM with fp32 accumulation, fused bias, fp32 output.
// out[m,n] = sum_k g_X[m,k] * g_W[k,n] + bias[n]
// 128x128x32 CTA tile, 8 warps in 2x4 (64x32 warp tile), m16n8k16 mma.
// 2-stage cp.async double buffer.
// ---------------------------------------------------------------------------
__global__ void __launch_bounds__(256, 2)
gemm_kernel(const float* __restrict__ bias,
            float* __restrict__ out)
{
    __shared__ __half sA[2][BM][BK + PADA];   // stride 40 halves (80B)
    __shared__ __half sB[2][BK][BN + PADB];   // stride 136 halves (272B)

    const int tid  = threadIdx.x;
    const int wid  = tid >> 5;
    const int lane = tid & 31;
    const int bm0  = blockIdx.x * BM;
    const int bn0  = blockIdx.y * BN;

    const int wm = (wid >> 2) * 64;   // warp row offset in tile
    const int wn = (wid & 3) * 32;    // warp col offset in tile

    float acc[4][4][4];
#pragma unroll
    for (int i = 0; i < 4; i++)
#pragma unroll
        for (int j = 0; j < 4; j++)
#pragma unroll
            for (int r = 0; r < 4; r++) acc[i][j][r] = 0.f;

    const __half* gA = g_X + (size_t)bm0 * K_DIM;

    // A: 128 rows x 4 16B-chunks = 512 tasks; B: 32 rows x 16 chunks = 512 tasks
    const int a_r0 = (tid) >> 2,        a_c0 = (tid & 3);
    const int a_r1 = (tid + 256) >> 2,  a_c1 = ((tid + 256) & 3);
    const int b_r0 = (tid) >> 4,        b_c0 = (tid & 15);
    const int b_r1 = (tid + 256) >> 4,  b_c1 = ((tid + 256) & 15);

#define ISSUE_STAGE(s, kt)                                                          \
    do {                                                                            \
        int kk = (kt) * BK;                                                         \
        uint32_t dA0 = (uint32_t)__cvta_generic_to_shared(&sA[s][a_r0][a_c0 * 8]);  \
        CP_ASYNC_CG(dA0, gA + (size_t)a_r0 * K_DIM + kk + a_c0 * 8);                \
        uint32_t dA1 = (uint32_t)__cvta_generic_to_shared(&sA[s][a_r1][a_c1 * 8]);  \
        CP_ASYNC_CG(dA1, gA + (size_t)a_r1 * K_DIM + kk + a_c1 * 8);                \
        uint32_t dB0 = (uint32_t)__cvta_generic_to_shared(&sB[s][b_r0][b_c0 * 8]);  \
        CP_ASYNC_CG(dB0, &g_W[(size_t)(kk + b_r0) * N_DIM + bn0 + b_c0 * 8]);       \
        uint32_t dB1 = (uint32_t)__cvta_generic_to_shared(&sB[s][b_r1][b_c1 * 8]);  \
        CP_ASYNC_CG(dB1, &g_W[(size_t)(kk + b_r1) * N_DIM + bn0 + b_c1 * 8]);       \
        CP_COMMIT();                                                                \
    } while (0)

    const int KT = K_DIM / BK;   // 128
    ISSUE_STAGE(0, 0);

    for (int kt = 0; kt < KT; kt++) {
        if (kt + 1 < KT) {
            ISSUE_STAGE((kt + 1) & 1, kt + 1);
            CP_WAIT(1);
        } else {
            CP_WAIT(0);
        }
        __syncthreads();

        const int s = kt & 1;
#pragma unroll
        for (int ks = 0; ks < 2; ks++) {
            const int k16 = ks * 16;
            uint32_t a[4][4];
#pragma unroll
            for (int mi = 0; mi < 4; mi++) {
                uint32_t addr = (uint32_t)__cvta_generic_to_shared(
                    &sA[s][wm + mi * 16 + (lane & 15)][k16 + 8 * (lane >> 4)]);
                asm volatile(
                    "ldmatrix.sync.aligned.m8n8.x4.shared.b16 {%0,%1,%2,%3}, [%4];"
                    : "=r"(a[mi][0]), "=r"(a[mi][1]), "=r"(a[mi][2]), "=r"(a[mi][3])
                    : "r"(addr));
            }
            uint32_t b[4][2];
#pragma unroll
            for (int nj = 0; nj < 2; nj++) {
                uint32_t t0, t1, t2, t3;
                uint32_t addr = (uint32_t)__cvta_generic_to_shared(
                    &sB[s][k16 + (lane & 15)][wn + nj * 16 + 8 * (lane >> 4)]);
                asm volatile(
                    "ldmatrix.sync.aligned.m8n8.x4.trans.shared.b16 {%0,%1,%2,%3}, [%4];"
                    : "=r"(t0), "=r"(t1), "=r"(t2), "=r"(t3)
                    : "r"(addr));
                b[nj * 2 + 0][0] = t0; b[nj * 2 + 0][1] = t1;
                b[nj * 2 + 1][0] = t2; b[nj * 2 + 1][1] = t3;
            }
#pragma unroll
            for (int mi = 0; mi < 4; mi++)
#pragma unroll
                for (int ni = 0; ni < 4; ni++) {
                    asm volatile(
                        "mma.sync.aligned.m16n8k16.row.col.f32.f16.f16.f32 "
                        "{%0,%1,%2,%3}, {%4,%5,%6,%7}, {%8,%9}, {%0,%1,%2,%3};"
                        : "+f"(acc[mi][ni][0]), "+f"(acc[mi][ni][1]),
                          "+f"(acc[mi][ni][2]), "+f"(acc[mi][ni][3])
                        : "r"(a[mi][0]), "r"(a[mi][1]), "r"(a[mi][2]), "r"(a[mi][3]),
                          "r"(b[ni][0]), "r"(b[ni][1]));
                }
        }
        __syncthreads();
    }

    // Epilogue: fp32 acc + fp32 bias -> fp16 round -> fp32 output, float2 stores
#pragma unroll
    for (int mi = 0; mi < 4; mi++) {
        int row0 = bm0 + wm + mi * 16 + (lane >> 2);
#pragma unroll
        for (int ni = 0; ni < 4; ni++) {
            int col = bn0 + wn + ni * 8 + (lane & 3) * 2;
            float2 bb = *reinterpret_cast<const float2*>(bias + col);
            // Match reference numerics: result is fp16-rounded (ref output is fp16)
            float r00 = __half2float(__float2half(acc[mi][ni][0] + bb.x));
            float r01 = __half2float(__float2half(acc[mi][ni][1] + bb.y));
            float r10 = __half2float(__float2half(acc[mi][ni][2] + bb.x));
            float r11 = __half2float(__float2half(acc[mi][ni][3] + bb.y));
            *reinterpret_cast<float2*>(out + (size_t)row0 * N_DIM + col) =
                make_float2(r00, r01);
            *reinterpret_cast<float2*>(out + (size_t)(row0 + 8) * N_DIM + col) =
                make_float2(r10, r11);
        }
    }
}

// ---------------------------------------------------------------------------
// Inputs (metadata order): x fp32, qweight int32, qzeros int32, scales fp32,
// bias fp32. Output fp32 (harness transports fp16 tensors as float32).
// ---------------------------------------------------------------------------
extern "C" void kernel_launch(void* const* d_in, const int* in_sizes, int n_in,
                              void* d_out, int out_size)
{
    const float* x    = (const float*)d_in[0];
    const int*   qw   = (const int*)d_in[1];
    const int*   qz   = (const int*)d_in[2];
    const float* sc   = (const float*)d_in[3];
    const float* bias = (const float*)d_in[4];
    float*       out  = (float*)d_out;

    const size_t xtotal = (size_t)M_DIM * K_DIM;
    convert_x_kernel<<<(unsigned)((xtotal / 8 + 255) / 256), 256>>>(x);

    const int total = K_DIM * NPACK;
    dequant_kernel<<<(total + 255) / 256, 256>>>(qw, qz, sc);

    dim3 grid(M_DIM / BM, N_DIM / BN);   // (64, 86)
    gemm_kernel<<<grid, 256>>>(bias, out);
}